// round 1
// baseline (speedup 1.0000x reference)
#include <cuda_runtime.h>
#include <cstddef>

// Correlation cost volume, B=8 C=96 H=64 W=96, D=21x21, stride2, maxdisp 20.
// out[b, i*21+j, y, x] = scale * sum_c d1[b,c,y,x]*d2[b,c,y+2(i-10),x+2(j-10)]
// scale = s1*s2/(96*out_scale)

#define NT      256
#define CC      8          // channels per smem chunk
#define NCH     12         // 96 / CC
#define GDY     7          // dy values processed concurrently
#define NGY     3          // 21 / GDY
#define TP      4          // x-pairs per thread
#define TD      7          // dx per thread
#define NXG     12         // 48 x-pairs / TP
#define NDXG    3          // 21 dx / TD
#define ACTIVE  252        // NXG*NDXG*GDY
#define NV      (TP+TD-1)  // 10 d2 pairs per thread per c

// Pad-swizzled rows: pair p stored at float offset 2*p + 2*(p>>2).
// d1: 48 pairs -> max 116 -> 120 floats. d2: 68 pairs (x' in [-20,116)) -> max 166 -> 168.
#define D1ROW   120
#define D2ROW   168

__device__ __forceinline__ unsigned long long ld_u64(const float* p) {
    return *reinterpret_cast<const unsigned long long*>(p);
}

__global__ void __launch_bounds__(NT, 2) corr_kernel(
    const float* __restrict__ d1g, const float* __restrict__ d2g,
    const float* __restrict__ s1, const float* __restrict__ s2,
    const float* __restrict__ osc, float* __restrict__ out)
{
    __shared__ float d1s[CC][D1ROW];            // 3.75 KB
    __shared__ float d2s[GDY][CC][D2ROW];       // 36.75 KB

    const int y   = blockIdx.x;     // 0..63
    const int b   = blockIdx.y;     // 0..7
    const int tid = threadIdx.x;
    const int xg  = tid % NXG;                  // x-pair group: pairs 4*xg..4*xg+3
    const int dxg = (tid / NXG) % NDXG;         // dx group: j = 7*dxg..7*dxg+6
    const int dyl = tid / (NXG * NDXG);         // local dy lane 0..7 (7 => inactive)
    const bool act = tid < ACTIVE;
    const int d0  = dxg * TD;

    const size_t b96 = (size_t)b * 96;

    for (int g = 0; g < NGY; ++g) {
        unsigned long long acc[TP][TD];
        #pragma unroll
        for (int pi = 0; pi < TP; ++pi)
            #pragma unroll
            for (int di = 0; di < TD; ++di) acc[pi][di] = 0ull;

        for (int cc = 0; cc < NCH; ++cc) {
            __syncthreads();   // protect smem from previous phase readers

            // ---- load d1 chunk [CC][96] (swizzled) ----
            for (int idx = tid; idx < CC * 96; idx += NT) {
                int c = idx / 96, x = idx - c * 96;
                int p = x >> 1, lo = x & 1;
                d1s[c][2*p + 2*(p>>2) + lo] =
                    d1g[((b96 + cc*CC + c) * 64 + y) * 96 + x];
            }
            // ---- load d2 chunk [GDY][CC][136], zero-filled OOB, swizzled ----
            for (int idx = tid; idx < GDY * CC * 136; idx += NT) {
                int f = idx % 136;
                int t = idx / 136;
                int c = t % CC;
                int r = t / CC;
                int i = g * GDY + r;            // dy index 0..20
                int row = y + 2 * (i - 10);
                int xx = f - 20;
                float v = 0.0f;
                if (((unsigned)row < 64u) && ((unsigned)xx < 96u))
                    v = d2g[((b96 + cc*CC + c) * 64 + row) * 96 + xx];
                int p = f >> 1, lo = f & 1;
                d2s[r][c][2*p + 2*(p>>2) + lo] = v;
            }
            __syncthreads();

            if (act) {
                #pragma unroll
                for (int c = 0; c < CC; ++c) {
                    const float* arow = d1s[c];
                    const float* vrow = d2s[dyl][c];
                    unsigned long long a[TP];
                    #pragma unroll
                    for (int pi = 0; pi < TP; ++pi)
                        a[pi] = ld_u64(arow + 10*xg + 2*pi);   // pair 4*xg+pi
                    unsigned long long v[NV];
                    #pragma unroll
                    for (int k = 0; k < NV; ++k) {
                        int pp = 4*xg + d0 + k;                // d2 pair = op + j
                        v[k] = ld_u64(vrow + 2*pp + 2*(pp>>2));
                    }
                    #pragma unroll
                    for (int pi = 0; pi < TP; ++pi)
                        #pragma unroll
                        for (int di = 0; di < TD; ++di)
                            asm("fma.rn.f32x2 %0, %1, %2, %0;"
                                : "+l"(acc[pi][di])
                                : "l"(a[pi]), "l"(v[pi + di]));
                }
            }
        }

        // ---- epilogue for this dy group ----
        if (act) {
            float sc = s1[0] * s2[0] / (96.0f * osc[0]);
            int i = g * GDY + dyl;
            #pragma unroll
            for (int pi = 0; pi < TP; ++pi) {
                int x = 2 * (4*xg + pi);
                #pragma unroll
                for (int di = 0; di < TD; ++di) {
                    int j = d0 + di;
                    int ch = i * 21 + j;
                    unsigned long long u = acc[pi][di];
                    float2 r;
                    r.x = __uint_as_float((unsigned)(u & 0xffffffffu)) * sc;
                    r.y = __uint_as_float((unsigned)(u >> 32)) * sc;
                    *reinterpret_cast<float2*>(
                        out + (((size_t)b * 441 + ch) * 64 + y) * 96 + x) = r;
                }
            }
        }
    }
}

extern "C" void kernel_launch(void* const* d_in, const int* in_sizes, int n_in,
                              void* d_out, int out_size) {
    const float* data1     = (const float*)d_in[0];
    const float* data2     = (const float*)d_in[1];
    const float* scale1    = (const float*)d_in[2];
    const float* scale2    = (const float*)d_in[3];
    /* d_in[4] = inter_scale, unused by the reference math */
    const float* out_scale = (const float*)d_in[5];

    dim3 grid(64, 8);   // (y, b)
    corr_kernel<<<grid, NT>>>(data1, data2, scale1, scale2, out_scale,
                              (float*)d_out);
}

// round 2
// speedup vs baseline: 1.9714x; 1.9714x over previous
#include <cuda_runtime.h>
#include <cstddef>

// Correlation cost volume, B=8 C=96 H=64 W=96, D=21x21, stride2, maxdisp 20.
// out[b, i*21+j, y, x] = scale * sum_c d1[b,c,y,x]*d2[b,c,y+2(i-10),x+2(j-10)]
// scale = s1*s2/(96*out_scale)
//
// Grid: (y=64, b=8, g=3). Each block handles one y row and one group of 7 dy.
// Smem: full d1 row (96 ch x 48 pairs, pad-swizzled) loaded once per block;
//       d2 chunk of 8 channels x 7 rows, double-barriered per chunk.
// Pad-swizzle: pair p at float offset 2p + 2(p>>2)  (conflict-mitigating).

#define NT      256
#define CC      8
#define NCH     12
#define GDY     7
#define TP      4
#define TD      7
#define NXG     12
#define NDXG    3
#define ACTIVE  252
#define NV      10          // TP+TD-1 d2 pairs per thread per channel

#define D1ROW   120         // 48 pairs swizzled -> max 116
#define D2ROW   168         // 68 pairs swizzled -> max 166
#define D1FLOATS (96 * D1ROW)              // 11520
#define D2FLOATS (GDY * CC * D2ROW)        // 9408
#define SMEM_FLOATS (D1FLOATS + D2FLOATS)  // 20928 -> 83712 B

__device__ __forceinline__ unsigned long long ld_u64(const float* p) {
    return *reinterpret_cast<const unsigned long long*>(p);
}

__global__ void __launch_bounds__(NT, 2) corr_kernel(
    const float* __restrict__ d1g, const float* __restrict__ d2g,
    const float* __restrict__ s1, const float* __restrict__ s2,
    const float* __restrict__ osc, float* __restrict__ out)
{
    extern __shared__ float sm[];
    float* sm_d1 = sm;              // [96][D1ROW]
    float* sm_d2 = sm + D1FLOATS;   // [GDY][CC][D2ROW]

    const int y   = blockIdx.x;     // 0..63
    const int b   = blockIdx.y;     // 0..7
    const int g   = blockIdx.z;     // 0..2  (dy group: i = 7g..7g+6)
    const int tid = threadIdx.x;

    // compute mapping
    const int xg  = tid % NXG;
    const int dxg = (tid / NXG) % NDXG;
    const int dyl = tid / (NXG * NDXG);
    const bool act = tid < ACTIVE;
    const int d0  = dxg * TD;

    // loader mapping
    const int lr   = tid >> 5;      // 0..7 (7 == spare)
    const int lane = tid & 31;

    const size_t b96 = (size_t)b * 96;

    // ---- zero-fill d2 buffer once (pads + invalid rows stay zero) ----
    {
        float4 z = make_float4(0.f, 0.f, 0.f, 0.f);
        float4* p = reinterpret_cast<float4*>(sm_d2);
        for (int i = tid; i < D2FLOATS / 4; i += NT) p[i] = z;
    }

    // ---- load full d1 row: 96 channels x 48 pairs (float2), swizzled ----
    {
        const int c8 = tid >> 5;                     // 0..7
        // pair p1 = lane -> floats 2*lane..; pair p2 = lane+32 (lane<16)
        const int s1o = 2 * lane + 2 * (lane >> 2);
        const int p2  = lane + 32;
        const int s2o = 2 * p2 + 2 * (p2 >> 2);
        #pragma unroll
        for (int it = 0; it < 12; ++it) {
            int c = it * 8 + c8;
            const float* gp = d1g + ((b96 + c) * 64 + y) * 96;
            float* srow = sm_d1 + c * D1ROW;
            float2 v1 = reinterpret_cast<const float2*>(gp)[lane];
            *reinterpret_cast<float2*>(srow + s1o) = v1;
            if (lane < 16) {
                float2 v2 = reinterpret_cast<const float2*>(gp)[p2];
                *reinterpret_cast<float2*>(srow + s2o) = v2;
            }
        }
    }

    // ---- precompute d2 loader state (once) ----
    // valid d2 pairs: p in [10,58): x' = 2p-20 in [0,96)
    int   row       = y + 2 * (g * GDY + lr) - 20;
    bool  ldr_valid = (lr < GDY) && ((unsigned)row < 64u);
    const float2* grow0 = reinterpret_cast<const float2*>(
        d2g + (b96 * 64 + (size_t)(ldr_valid ? row : 0)) * 96);
    // slot offsets (floats) within a d2 smem row
    const int pA = 10 + lane, pB = 42 + lane;
    const int sA = 2 * pA + 2 * (pA >> 2);
    const int sB = 2 * pB + 2 * (pB >> 2);
    float* sdst = sm_d2 + lr * (CC * D2ROW);

    // ---- precompute compute-phase smem offsets ----
    int voff[NV];
    {
        const int P0 = 4 * xg + d0;
        #pragma unroll
        for (int k = 0; k < NV; ++k) {
            int P = P0 + k;
            voff[k] = 2 * P + 2 * (P >> 2);
        }
    }
    const int aoff = 10 * xg;

    // ---- accumulators ----
    unsigned long long acc[TP][TD];
    #pragma unroll
    for (int pi = 0; pi < TP; ++pi)
        #pragma unroll
        for (int di = 0; di < TD; ++di) acc[pi][di] = 0ull;

    // ---- main loop over channel chunks ----
    for (int cc = 0; cc < NCH; ++cc) {
        __syncthreads();   // previous chunk's readers done
        if (ldr_valid) {
            const float2* gp = grow0 + (size_t)(cc * CC) * (64 * 96 / 2);
            float* sp = sdst;
            #pragma unroll
            for (int c = 0; c < CC; ++c) {
                float2 vA = gp[lane];
                *reinterpret_cast<float2*>(sp + sA) = vA;
                if (lane < 16) {
                    float2 vB = gp[32 + lane];
                    *reinterpret_cast<float2*>(sp + sB) = vB;
                }
                gp += 64 * 96 / 2;
                sp += D2ROW;
            }
        }
        __syncthreads();

        if (act) {
            const float* arow = sm_d1 + (cc * CC) * D1ROW + aoff;
            const float* vrow = sm_d2 + dyl * (CC * D2ROW);
            #pragma unroll
            for (int c = 0; c < CC; ++c) {
                unsigned long long a[TP];
                #pragma unroll
                for (int pi = 0; pi < TP; ++pi)
                    a[pi] = ld_u64(arow + 2 * pi);
                unsigned long long v[NV];
                #pragma unroll
                for (int k = 0; k < NV; ++k)
                    v[k] = ld_u64(vrow + voff[k]);
                #pragma unroll
                for (int pi = 0; pi < TP; ++pi)
                    #pragma unroll
                    for (int di = 0; di < TD; ++di)
                        asm("fma.rn.f32x2 %0, %1, %2, %0;"
                            : "+l"(acc[pi][di])
                            : "l"(a[pi]), "l"(v[pi + di]));
                arow += D1ROW;
                vrow += D2ROW;
            }
        }
    }

    // ---- epilogue ----
    if (act) {
        float sc = s1[0] * s2[0] / (96.0f * osc[0]);
        int i = g * GDY + dyl;
        #pragma unroll
        for (int pi = 0; pi < TP; ++pi) {
            int x = 2 * (4 * xg + pi);
            #pragma unroll
            for (int di = 0; di < TD; ++di) {
                int j = d0 + di;
                int ch = i * 21 + j;
                unsigned long long u = acc[pi][di];
                float2 r;
                r.x = __uint_as_float((unsigned)(u & 0xffffffffu)) * sc;
                r.y = __uint_as_float((unsigned)(u >> 32)) * sc;
                *reinterpret_cast<float2*>(
                    out + (((size_t)b * 441 + ch) * 64 + y) * 96 + x) = r;
            }
        }
    }
}

extern "C" void kernel_launch(void* const* d_in, const int* in_sizes, int n_in,
                              void* d_out, int out_size) {
    const float* data1     = (const float*)d_in[0];
    const float* data2     = (const float*)d_in[1];
    const float* scale1    = (const float*)d_in[2];
    const float* scale2    = (const float*)d_in[3];
    /* d_in[4] = inter_scale, unused by the reference math */
    const float* out_scale = (const float*)d_in[5];

    size_t smem = SMEM_FLOATS * sizeof(float);
    cudaFuncSetAttribute(corr_kernel,
                         cudaFuncAttributeMaxDynamicSharedMemorySize, (int)smem);

    dim3 grid(64, 8, 3);   // (y, b, dy-group)
    corr_kernel<<<grid, NT, smem>>>(data1, data2, scale1, scale2, out_scale,
                                    (float*)d_out);
}